// round 7
// baseline (speedup 1.0000x reference)
#include <cuda_runtime.h>
#include <cuda_fp16.h>
#include <math.h>

// ---------------- static problem config ----------------
#define BN      960
#define P       144
#define DIM     192
#define HEADS   6
#define DH      32
#define WT      64
#define MW      15
#define PSQ     (P * P)
#define M_TOT   (BN * P)          // 138240
#define SCALE   0.1767766952966369f
#define LOG2E   1.4426950408889634f

// ---------------- scratch ----------------
__device__ unsigned g_qkv_h[(size_t)3 * BN * HEADS * P * DH / 2];   // 159 MB
__device__ unsigned g_xo_h[(size_t)M_TOT * DIM / 2];                // 53 MB
__device__ unsigned g_wq_h[576 * 192 / 2];
__device__ unsigned g_wp_h[192 * 192 / 2];
__device__ unsigned g_bias_h[(size_t)WT * HEADS * PSQ / 2];         // 16 MB
__device__ unsigned g_mask_h[(size_t)BN * PSQ / 2];                 // 40 MB

// ---------------- helpers ----------------
__device__ __forceinline__ unsigned ph2(float a, float b) {
    __half2 h = __floats2half2_rn(a, b);
    return *(unsigned*)&h;
}
__device__ __forceinline__ float ex2(float x) {
    float y;
    asm("ex2.approx.f32 %0, %1;" : "=f"(y) : "f"(x));
    return y;
}
__device__ __forceinline__ void mma_f16(float c[4], const unsigned a[4], const unsigned b[2]) {
    asm volatile(
        "mma.sync.aligned.m16n8k16.row.col.f32.f16.f16.f32 "
        "{%0,%1,%2,%3}, {%4,%5,%6,%7}, {%8,%9}, {%0,%1,%2,%3};"
        : "+f"(c[0]), "+f"(c[1]), "+f"(c[2]), "+f"(c[3])
        : "r"(a[0]), "r"(a[1]), "r"(a[2]), "r"(a[3]), "r"(b[0]), "r"(b[1]));
}
__device__ __forceinline__ void ldsm4(unsigned r[4], unsigned saddr) {
    asm volatile("ldmatrix.sync.aligned.m8n8.x4.shared.b16 {%0,%1,%2,%3}, [%4];"
                 : "=r"(r[0]), "=r"(r[1]), "=r"(r[2]), "=r"(r[3]) : "r"(saddr));
}
__device__ __forceinline__ void cp_async16(void* smem, const void* gmem) {
    unsigned s = (unsigned)__cvta_generic_to_shared(smem);
    asm volatile("cp.async.ca.shared.global [%0], [%1], 16;" :: "r"(s), "l"(gmem));
}
#define CP_COMMIT() asm volatile("cp.async.commit_group;")
template<int N> __device__ __forceinline__ void cp_wait() {
    asm volatile("cp.async.wait_group %0;" :: "n"(N));
}

// ---------------- fused prep kernel ----------------
// regions (block ranges): [0, NB_B): bias  [NB_B, +NB_W): weights
//                         [.., +NB_X): x->half   [.., +NB_M): mask->half
#define NB_B 2592      // WT * PSQ/2 / 256 tasks
#define NB_W 16
#define NB_X 25920     // M_TOT*DIM/4 / 256
#define NB_M 19440     // BN*PSQ/4 / 256
#define NB_TOT (NB_B + NB_W + NB_X + NB_M)

__global__ void __launch_bounds__(256) prep_all(
    const float* __restrict__ x, const float* __restrict__ mask,
    const float* __restrict__ wq, const float* __restrict__ wp,
    const float* __restrict__ table) {
    const int b = blockIdx.x;
    if (b < NB_B) {
        // ---- bias densify: one thread per (wt, ij-pair), coalesced half2 writes
        const int id = b * 256 + threadIdx.x;           // < WT * PSQ/2
        const int wt = id / (PSQ / 2), jp = id % (PSQ / 2);
        const int ij0 = 2 * jp;
        const int i = ij0 / P, j0 = ij0 % P;            // j0 even, j0+1 same row
        const int zi = i / 72, hi_ = (i / 12) % 6, wi = i % 12;
        const int rowterm = zi * 828 + hi_ * 23 + wi + 11;
        const int j1 = j0 + 1;
        const int pos0 = rowterm + (j0 / 72) * 1656 + ((j0 / 12) % 6) * 138 - (j0 % 12);
        const int pos1 = rowterm + (j1 / 72) * 1656 + ((j1 / 12) % 6) * 138 - (j1 % 12);
        const float* s0 = table + (size_t)pos0 * (WT * HEADS) + wt * HEADS;
        const float* s1 = table + (size_t)pos1 * (WT * HEADS) + wt * HEADS;
        unsigned* dst = g_bias_h + (size_t)wt * HEADS * (PSQ / 2) + jp;
#pragma unroll
        for (int h = 0; h < HEADS; h++)
            dst[(size_t)h * (PSQ / 2)] = ph2(__ldg(s0 + h) * LOG2E, __ldg(s1 + h) * LOG2E);
    } else if (b < NB_B + NB_W) {
        // ---- weights -> half, transposed to [n][k]
        const int gid = (b - NB_B) * 256 + threadIdx.x;
        const int stride = NB_W * 256;
        for (int i = gid; i < 576 * 96; i += stride) {
            const int n = i / 96, k = (i % 96) * 2;
            g_wq_h[n * 96 + (k >> 1)] = ph2(wq[(size_t)k * 576 + n], wq[(size_t)(k + 1) * 576 + n]);
        }
        for (int i = gid; i < 192 * 96; i += stride) {
            const int n = i / 96, k = (i % 96) * 2;
            g_wp_h[n * 96 + (k >> 1)] = ph2(wp[(size_t)k * 192 + n], wp[(size_t)(k + 1) * 192 + n]);
        }
    } else if (b < NB_B + NB_W + NB_X) {
        // ---- x -> half
        const int i = (b - NB_B - NB_W) * 256 + threadIdx.x;
        float4 v = ((const float4*)x)[i];
        uint2 o;
        o.x = ph2(v.x, v.y);
        o.y = ph2(v.z, v.w);
        ((uint2*)g_xo_h)[i] = o;
    } else {
        // ---- mask -> half * log2e
        const int i = (b - NB_B - NB_W - NB_X) * 256 + threadIdx.x;
        float4 v = ((const float4*)mask)[i];
        uint2 o;
        o.x = ph2(v.x * LOG2E, v.y * LOG2E);
        o.y = ph2(v.z * LOG2E, v.w * LOG2E);
        ((uint2*)g_mask_h)[i] = o;
    }
}

// ---------------- fp16 mma GEMM (ldmatrix), 256x64 block tile ----------------
// 8 warps (4x2), warp tile 64x32, k-slab 64, double buffered cp.async.
template<bool IS_QKV>
__global__ void __launch_bounds__(256) gemm_h(const float* __restrict__ bias,
                                              float* __restrict__ out) {
    extern __shared__ __half smh[];
    __half* As = smh;                    // [2][256*72]
    __half* Bs = smh + 2 * 256 * 72;     // [2][64*72]
    const __half* X = (const __half*)g_xo_h;
    const __half* W = IS_QKV ? (const __half*)g_wq_h : (const __half*)g_wp_h;

    const int bm = blockIdx.y * 256, bn = blockIdx.x * 64;
    const int tid = threadIdx.x;
    const int w = tid >> 5, lane = tid & 31;
    const int g = lane >> 2, t = lane & 3;
    const int m0 = (w & 3) * 64, n0 = (w >> 2) * 32;

    const int arow = m0 + (lane & 15);
    const int acol = (lane >> 4) * 8;
    const int brow = n0 + (lane >> 4) * 8 + (lane & 7);
    const int bcol = ((lane >> 3) & 1) * 8;

    float cc[4][4][4] = {};

#define ISSUE_TILE(buf, k0)                                                       \
    {                                                                             \
        __half* Ab = As + (buf) * 256 * 72;                                       \
        _Pragma("unroll")                                                         \
        for (int i = 0; i < 8; i++) {                                             \
            const int idx = tid + 256 * i;                                        \
            const int r = idx >> 3, c = (idx & 7) * 8;                            \
            cp_async16(Ab + r * 72 + c, X + (size_t)(bm + r) * 192 + (k0) + c);   \
        }                                                                         \
        __half* Bb = Bs + (buf) * 64 * 72;                                        \
        _Pragma("unroll")                                                         \
        for (int i = 0; i < 2; i++) {                                             \
            const int idx = tid + 256 * i;                                        \
            const int r = idx >> 3, c = (idx & 7) * 8;                            \
            cp_async16(Bb + r * 72 + c, W + (size_t)(bn + r) * 192 + (k0) + c);   \
        }                                                                         \
    }

    ISSUE_TILE(0, 0);
    CP_COMMIT();

#pragma unroll
    for (int it = 0; it < 3; ++it) {
        if (it < 2) {
            ISSUE_TILE((it + 1) & 1, 64 * (it + 1));
            CP_COMMIT();
            cp_wait<1>();
        } else {
            cp_wait<0>();
        }
        __syncthreads();
        const unsigned sA = (unsigned)__cvta_generic_to_shared(As + (it & 1) * 256 * 72);
        const unsigned sB = (unsigned)__cvta_generic_to_shared(Bs + (it & 1) * 64 * 72);
#pragma unroll
        for (int kk = 0; kk < 64; kk += 16) {
            unsigned af[4][4], bf[4][2];
#pragma unroll
            for (int mt = 0; mt < 4; mt++)
                ldsm4(af[mt], sA + ((arow + mt * 16) * 72 + kk + acol) * 2);
#pragma unroll
            for (int nt2 = 0; nt2 < 2; nt2++) {
                unsigned r[4];
                ldsm4(r, sB + ((brow + nt2 * 16) * 72 + kk + bcol) * 2);
                bf[nt2 * 2][0] = r[0]; bf[nt2 * 2][1] = r[1];
                bf[nt2 * 2 + 1][0] = r[2]; bf[nt2 * 2 + 1][1] = r[3];
            }
#pragma unroll
            for (int mt = 0; mt < 4; mt++)
#pragma unroll
                for (int nt = 0; nt < 4; nt++)
                    mma_f16(cc[mt][nt], af[mt], bf[nt]);
        }
        __syncthreads();
    }
#undef ISSUE_TILE

    // epilogue
#pragma unroll
    for (int mt = 0; mt < 4; mt++) {
#pragma unroll
        for (int half_ = 0; half_ < 2; half_++) {
            const int m = bm + m0 + mt * 16 + g + half_ * 8;
            if (IS_QKV) {
                const int b_ = m / P, p = m % P;
#pragma unroll
                for (int nt = 0; nt < 4; nt++) {
                    const int n = bn + n0 + nt * 8 + 2 * t;
                    const int part = n / DIM, cp = n % DIM;
                    const int h = cp >> 5, d = cp & 31;
                    float v0 = cc[mt][nt][half_ * 2 + 0];
                    float v1 = cc[mt][nt][half_ * 2 + 1];
                    if (part == 0) { v0 *= SCALE * LOG2E; v1 *= SCALE * LOG2E; }
                    const size_t di = ((((size_t)part * BN + b_) * HEADS + h) * P + p) * DH + d;
                    *(unsigned*)((__half*)g_qkv_h + di) = ph2(v0, v1);
                }
            } else {
#pragma unroll
                for (int nt = 0; nt < 4; nt++) {
                    const int n = bn + n0 + nt * 8 + 2 * t;
                    float2 st;
                    st.x = cc[mt][nt][half_ * 2 + 0] + __ldg(bias + n);
                    st.y = cc[mt][nt][half_ * 2 + 1] + __ldg(bias + n + 1);
                    *(float2*)(out + (size_t)m * DIM + n) = st;
                }
            }
        }
    }
}

// ---------------- attention ----------------
__global__ void __launch_bounds__(288, 2) attn_h(int dummy) {
    __shared__ __align__(16) __half qs[144 * 40];
    __shared__ __align__(16) __half ks[144 * 40];
    __shared__ __align__(16) __half vT[32 * 152];

    const int bh = blockIdx.x;
    const int bn = bh / HEADS, h = bh % HEADS;
    const int wt = bn / MW;
    const int tid = threadIdx.x;
    const int w = tid >> 5, lane = tid & 31;
    const int g = lane >> 2, t = lane & 3;

    const size_t hp = (size_t)P * DH;
    const size_t plane = (size_t)BN * HEADS * hp;
    const size_t qbase = ((size_t)bn * HEADS + h) * hp;
    const __half* gq = (const __half*)g_qkv_h + qbase;
    const __half* gk = (const __half*)g_qkv_h + plane + qbase;
    const __half* gv = (const __half*)g_qkv_h + 2 * plane + qbase;

    for (int f = tid; f < 576; f += 288) {
        const int p = f >> 2, c = (f & 3) * 8;
        *(uint4*)(qs + p * 40 + c) = *(const uint4*)(gq + p * 32 + c);
        *(uint4*)(ks + p * 40 + c) = *(const uint4*)(gk + p * 32 + c);
    }
    for (int f = tid; f < 2304; f += 288) {
        const int p = f >> 4, d = (f & 15) * 2;
        __half2 v2 = *(const __half2*)(gv + p * 32 + d);
        vT[d * 152 + p] = __low2half(v2);
        vT[(d + 1) * 152 + p] = __high2half(v2);
    }
    __syncthreads();

    const int wr = w * 16;
    const unsigned sQ = (unsigned)__cvta_generic_to_shared(qs);
    const unsigned sK = (unsigned)__cvta_generic_to_shared(ks);
    const unsigned sV = (unsigned)__cvta_generic_to_shared(vT);

    const int qrow = wr + (lane & 15);
    const int qcol = (lane >> 4) * 8;
    const int krow = (lane >> 4) * 8 + (lane & 7);
    const int kcol = ((lane >> 3) & 1) * 8;

    // ---- S = Q @ K^T ----
    float s[18][4] = {};
#pragma unroll
    for (int kk = 0; kk < DH; kk += 16) {
        unsigned af[4];
        ldsm4(af, sQ + (qrow * 40 + kk + qcol) * 2);
#pragma unroll
        for (int nt2 = 0; nt2 < 9; nt2++) {
            unsigned r[4];
            ldsm4(r, sK + ((krow + nt2 * 16) * 40 + kk + kcol) * 2);
            unsigned b0[2] = { r[0], r[1] };
            unsigned b1[2] = { r[2], r[3] };
            mma_f16(s[2 * nt2], af, b0);
            mma_f16(s[2 * nt2 + 1], af, b1);
        }
    }

    // ---- + bias + mask (fp16, pre-scaled by log2e) ----
    {
        const __half* gb = (const __half*)g_bias_h + ((size_t)(wt * HEADS + h)) * PSQ;
        const __half* mk = (const __half*)g_mask_h + (size_t)bn * PSQ;
        const int r0 = wr + g, r1 = r0 + 8;
#pragma unroll
        for (int nt = 0; nt < 18; nt++) {
            const int c = nt * 8 + 2 * t;
            __half2 a0 = __hadd2(*(const __half2*)(gb + (size_t)r0 * P + c),
                                 *(const __half2*)(mk + (size_t)r0 * P + c));
            __half2 a1 = __hadd2(*(const __half2*)(gb + (size_t)r1 * P + c),
                                 *(const __half2*)(mk + (size_t)r1 * P + c));
            float2 f0 = __half22float2(a0);
            float2 f1 = __half22float2(a1);
            s[nt][0] += f0.x; s[nt][1] += f0.y;
            s[nt][2] += f1.x; s[nt][3] += f1.y;
        }
    }

    // ---- softmax (base-2 domain) ----
    {
        float mx0 = -1e30f, mx1 = -1e30f;
#pragma unroll
        for (int nt = 0; nt < 18; nt++) {
            mx0 = fmaxf(mx0, fmaxf(s[nt][0], s[nt][1]));
            mx1 = fmaxf(mx1, fmaxf(s[nt][2], s[nt][3]));
        }
        mx0 = fmaxf(mx0, __shfl_xor_sync(0xffffffffu, mx0, 1));
        mx0 = fmaxf(mx0, __shfl_xor_sync(0xffffffffu, mx0, 2));
        mx1 = fmaxf(mx1, __shfl_xor_sync(0xffffffffu, mx1, 1));
        mx1 = fmaxf(mx1, __shfl_xor_sync(0xffffffffu, mx1, 2));
        float s0 = 0.f, s1 = 0.f;
#pragma unroll
        for (int nt = 0; nt < 18; nt++) {
            s[nt][0] = ex2(s[nt][0] - mx0);
            s[nt][1] = ex2(s[nt][1] - mx0);
            s[nt][2] = ex2(s[nt][2] - mx1);
            s[nt][3] = ex2(s[nt][3] - mx1);
            s0 += s[nt][0] + s[nt][1];
            s1 += s[nt][2] + s[nt][3];
        }
        s0 += __shfl_xor_sync(0xffffffffu, s0, 1);
        s0 += __shfl_xor_sync(0xffffffffu, s0, 2);
        s1 += __shfl_xor_sync(0xffffffffu, s1, 1);
        s1 += __shfl_xor_sync(0xffffffffu, s1, 2);
        const float i0 = 1.f / s0, i1 = 1.f / s1;
#pragma unroll
        for (int nt = 0; nt < 18; nt++) {
            s[nt][0] *= i0; s[nt][1] *= i0;
            s[nt][2] *= i1; s[nt][3] *= i1;
        }
    }

    // ---- O = S @ V (C-frag == A-frag) ----
    {
        float o[4][4] = {};
        const int vrow = (lane >> 4) * 8 + (lane & 7);
        const int vcol = ((lane >> 3) & 1) * 8;
#pragma unroll
        for (int kb = 0; kb < 9; kb++) {
            unsigned a[4];
            a[0] = ph2(s[2 * kb][0], s[2 * kb][1]);
            a[1] = ph2(s[2 * kb][2], s[2 * kb][3]);
            a[2] = ph2(s[2 * kb + 1][0], s[2 * kb + 1][1]);
            a[3] = ph2(s[2 * kb + 1][2], s[2 * kb + 1][3]);
#pragma unroll
            for (int nt2 = 0; nt2 < 2; nt2++) {
                unsigned r[4];
                ldsm4(r, sV + ((vrow + nt2 * 16) * 152 + kb * 16 + vcol) * 2);
                unsigned b0[2] = { r[0], r[1] };
                unsigned b1[2] = { r[2], r[3] };
                mma_f16(o[nt2 * 2], a, b0);
                mma_f16(o[nt2 * 2 + 1], a, b1);
            }
        }
        __half* go = (__half*)g_xo_h + ((size_t)bn * P) * DIM + h * 32;
#pragma unroll
        for (int nt = 0; nt < 4; nt++) {
            const int col = nt * 8 + 2 * t;
            *(unsigned*)(go + (size_t)(wr + g) * DIM + col)     = ph2(o[nt][0], o[nt][1]);
            *(unsigned*)(go + (size_t)(wr + g + 8) * DIM + col) = ph2(o[nt][2], o[nt][3]);
        }
    }
}

// ---------------- launcher ----------------
extern "C" void kernel_launch(void* const* d_in, const int* in_sizes, int n_in,
                              void* d_out, int out_size) {
    const float* x          = (const float*)d_in[0];
    const float* mask       = (const float*)d_in[1];
    const float* w_qkv      = (const float*)d_in[2];
    const float* w_proj     = (const float*)d_in[3];
    const float* b_proj     = (const float*)d_in[4];
    const float* bias_table = (const float*)d_in[5];
    float* out = (float*)d_out;

    const int smem_gemm = (2 * 256 * 72 + 2 * 64 * 72) * 2;   // 92160 B
    cudaFuncSetAttribute(gemm_h<true>,
                         cudaFuncAttributeMaxDynamicSharedMemorySize, smem_gemm);
    cudaFuncSetAttribute(gemm_h<false>,
                         cudaFuncAttributeMaxDynamicSharedMemorySize, smem_gemm);

    prep_all<<<NB_TOT, 256>>>(x, mask, w_qkv, w_proj, bias_table);
    gemm_h<true><<<dim3(9, M_TOT / 256), 256, smem_gemm>>>(nullptr, nullptr);
    attn_h<<<BN * HEADS, 288>>>(0);
    gemm_h<false><<<dim3(3, M_TOT / 256), 256, smem_gemm>>>(b_proj, out);
}

// round 9
// speedup vs baseline: 1.0716x; 1.0716x over previous
#include <cuda_runtime.h>
#include <cuda_fp16.h>
#include <math.h>

// ---------------- static problem config ----------------
#define BN      960
#define P       144
#define DIM     192
#define HEADS   6
#define DH      32
#define WT      64
#define MW      15
#define PSQ     (P * P)
#define M_TOT   (BN * P)          // 138240
#define SCALE   0.1767766952966369f
#define LOG2E   1.4426950408889634f

// ---------------- scratch ----------------
__device__ unsigned g_qkv_h[(size_t)3 * BN * HEADS * P * DH / 2];   // 159 MB
__device__ unsigned g_xo_h[(size_t)M_TOT * DIM / 2];                // 53 MB
__device__ unsigned g_wq_h[576 * 192 / 2];
__device__ unsigned g_wp_h[192 * 192 / 2];
__device__ unsigned g_bias_h[(size_t)WT * HEADS * PSQ / 2];         // 16 MB
__device__ unsigned g_mask_h[(size_t)BN * PSQ / 2];                 // 40 MB

// ---------------- helpers ----------------
__device__ __forceinline__ unsigned ph2(float a, float b) {
    __half2 h = __floats2half2_rn(a, b);
    return *(unsigned*)&h;
}
__device__ __forceinline__ unsigned ex2_h2(float a, float b) {
    // pack two f32 into f16x2, then one MUFU ex2 for both
    unsigned p = ph2(a, b), y;
    asm("ex2.approx.f16x2 %0, %1;" : "=r"(y) : "r"(p));
    return y;
}
__device__ __forceinline__ void mma_f16(float c[4], const unsigned a[4], const unsigned b[2]) {
    asm volatile(
        "mma.sync.aligned.m16n8k16.row.col.f32.f16.f16.f32 "
        "{%0,%1,%2,%3}, {%4,%5,%6,%7}, {%8,%9}, {%0,%1,%2,%3};"
        : "+f"(c[0]), "+f"(c[1]), "+f"(c[2]), "+f"(c[3])
        : "r"(a[0]), "r"(a[1]), "r"(a[2]), "r"(a[3]), "r"(b[0]), "r"(b[1]));
}
__device__ __forceinline__ void ldsm4(unsigned r[4], unsigned saddr) {
    asm volatile("ldmatrix.sync.aligned.m8n8.x4.shared.b16 {%0,%1,%2,%3}, [%4];"
                 : "=r"(r[0]), "=r"(r[1]), "=r"(r[2]), "=r"(r[3]) : "r"(saddr));
}
__device__ __forceinline__ void cp_async16(void* smem, const void* gmem) {
    unsigned s = (unsigned)__cvta_generic_to_shared(smem);
    asm volatile("cp.async.ca.shared.global [%0], [%1], 16;" :: "r"(s), "l"(gmem));
}
#define CP_COMMIT() asm volatile("cp.async.commit_group;")
template<int N> __device__ __forceinline__ void cp_wait() {
    asm volatile("cp.async.wait_group %0;" :: "n"(N));
}

// ---------------- fused prep kernel ----------------
#define NB_B 2592
#define NB_W 16
#define NB_X 25920
#define NB_M 19440
#define NB_TOT (NB_B + NB_W + NB_X + NB_M)

__global__ void __launch_bounds__(256) prep_all(
    const float* __restrict__ x, const float* __restrict__ mask,
    const float* __restrict__ wq, const float* __restrict__ wp,
    const float* __restrict__ table) {
    const int b = blockIdx.x;
    if (b < NB_B) {
        const int id = b * 256 + threadIdx.x;
        const int wt = id / (PSQ / 2), jp = id % (PSQ / 2);
        const int ij0 = 2 * jp;
        const int i = ij0 / P, j0 = ij0 % P;
        const int zi = i / 72, hi_ = (i / 12) % 6, wi = i % 12;
        const int rowterm = zi * 828 + hi_ * 23 + wi + 11;
        const int j1 = j0 + 1;
        const int pos0 = rowterm + (j0 / 72) * 1656 + ((j0 / 12) % 6) * 138 - (j0 % 12);
        const int pos1 = rowterm + (j1 / 72) * 1656 + ((j1 / 12) % 6) * 138 - (j1 % 12);
        const float* s0 = table + (size_t)pos0 * (WT * HEADS) + wt * HEADS;
        const float* s1 = table + (size_t)pos1 * (WT * HEADS) + wt * HEADS;
        unsigned* dst = g_bias_h + (size_t)wt * HEADS * (PSQ / 2) + jp;
#pragma unroll
        for (int h = 0; h < HEADS; h++)
            dst[(size_t)h * (PSQ / 2)] = ph2(__ldg(s0 + h) * LOG2E, __ldg(s1 + h) * LOG2E);
    } else if (b < NB_B + NB_W) {
        const int gid = (b - NB_B) * 256 + threadIdx.x;
        const int stride = NB_W * 256;
        for (int i = gid; i < 576 * 96; i += stride) {
            const int n = i / 96, k = (i % 96) * 2;
            g_wq_h[n * 96 + (k >> 1)] = ph2(wq[(size_t)k * 576 + n], wq[(size_t)(k + 1) * 576 + n]);
        }
        for (int i = gid; i < 192 * 96; i += stride) {
            const int n = i / 96, k = (i % 96) * 2;
            g_wp_h[n * 96 + (k >> 1)] = ph2(wp[(size_t)k * 192 + n], wp[(size_t)(k + 1) * 192 + n]);
        }
    } else if (b < NB_B + NB_W + NB_X) {
        const int i = (b - NB_B - NB_W) * 256 + threadIdx.x;
        float4 v = ((const float4*)x)[i];
        uint2 o;
        o.x = ph2(v.x, v.y);
        o.y = ph2(v.z, v.w);
        ((uint2*)g_xo_h)[i] = o;
    } else {
        const int i = (b - NB_B - NB_W - NB_X) * 256 + threadIdx.x;
        float4 v = ((const float4*)mask)[i];
        uint2 o;
        o.x = ph2(v.x * LOG2E, v.y * LOG2E);
        o.y = ph2(v.z * LOG2E, v.w * LOG2E);
        ((uint2*)g_mask_h)[i] = o;
    }
}

// ---------------- fp16 mma GEMM (ldmatrix), 128x64 block tile ----------------
template<bool IS_QKV>
__global__ void __launch_bounds__(256) gemm_h(const float* __restrict__ bias,
                                              float* __restrict__ out) {
    extern __shared__ __half smh[];
    __half* As = smh;                    // [2][128*72]
    __half* Bs = smh + 2 * 128 * 72;     // [2][64*72]
    const __half* X = (const __half*)g_xo_h;
    const __half* W = IS_QKV ? (const __half*)g_wq_h : (const __half*)g_wp_h;

    const int bm = blockIdx.y * 128, bn = blockIdx.x * 64;
    const int tid = threadIdx.x;
    const int w = tid >> 5, lane = tid & 31;
    const int g = lane >> 2, t = lane & 3;
    const int m0 = (w & 3) * 32, n0 = (w >> 2) * 32;

    const int arow = m0 + (lane & 15);
    const int acol = (lane >> 4) * 8;
    const int brow = n0 + (lane >> 4) * 8 + (lane & 7);
    const int bcol = ((lane >> 3) & 1) * 8;

    float cc[2][4][4] = {};

#define ISSUE_TILE(buf, k0)                                                       \
    {                                                                             \
        __half* Ab = As + (buf) * 128 * 72;                                       \
        _Pragma("unroll")                                                         \
        for (int i = 0; i < 4; i++) {                                             \
            const int idx = tid + 256 * i;                                        \
            const int r = idx >> 3, c = (idx & 7) * 8;                            \
            cp_async16(Ab + r * 72 + c, X + (size_t)(bm + r) * 192 + (k0) + c);   \
        }                                                                         \
        __half* Bb = Bs + (buf) * 64 * 72;                                        \
        _Pragma("unroll")                                                         \
        for (int i = 0; i < 2; i++) {                                             \
            const int idx = tid + 256 * i;                                        \
            const int r = idx >> 3, c = (idx & 7) * 8;                            \
            cp_async16(Bb + r * 72 + c, W + (size_t)(bn + r) * 192 + (k0) + c);   \
        }                                                                         \
    }

    ISSUE_TILE(0, 0);
    CP_COMMIT();

#pragma unroll
    for (int it = 0; it < 3; ++it) {
        if (it < 2) {
            ISSUE_TILE((it + 1) & 1, 64 * (it + 1));
            CP_COMMIT();
            cp_wait<1>();
        } else {
            cp_wait<0>();
        }
        __syncthreads();
        const unsigned sA = (unsigned)__cvta_generic_to_shared(As + (it & 1) * 128 * 72);
        const unsigned sB = (unsigned)__cvta_generic_to_shared(Bs + (it & 1) * 64 * 72);
#pragma unroll
        for (int kk = 0; kk < 64; kk += 16) {
            unsigned af[2][4], bf[4][2];
#pragma unroll
            for (int mt = 0; mt < 2; mt++)
                ldsm4(af[mt], sA + ((arow + mt * 16) * 72 + kk + acol) * 2);
#pragma unroll
            for (int nt2 = 0; nt2 < 2; nt2++) {
                unsigned r[4];
                ldsm4(r, sB + ((brow + nt2 * 16) * 72 + kk + bcol) * 2);
                bf[nt2 * 2][0] = r[0]; bf[nt2 * 2][1] = r[1];
                bf[nt2 * 2 + 1][0] = r[2]; bf[nt2 * 2 + 1][1] = r[3];
            }
#pragma unroll
            for (int mt = 0; mt < 2; mt++)
#pragma unroll
                for (int nt = 0; nt < 4; nt++)
                    mma_f16(cc[mt][nt], af[mt], bf[nt]);
        }
        __syncthreads();
    }
#undef ISSUE_TILE

    // epilogue
#pragma unroll
    for (int mt = 0; mt < 2; mt++) {
#pragma unroll
        for (int half_ = 0; half_ < 2; half_++) {
            const int m = bm + m0 + mt * 16 + g + half_ * 8;
            if (IS_QKV) {
                const int b_ = m / P, p = m % P;
#pragma unroll
                for (int nt = 0; nt < 4; nt++) {
                    const int n = bn + n0 + nt * 8 + 2 * t;
                    const int part = n / DIM, cp = n % DIM;
                    const int h = cp >> 5, d = cp & 31;
                    float v0 = cc[mt][nt][half_ * 2 + 0];
                    float v1 = cc[mt][nt][half_ * 2 + 1];
                    if (part == 0) { v0 *= SCALE * LOG2E; v1 *= SCALE * LOG2E; }
                    const size_t di = ((((size_t)part * BN + b_) * HEADS + h) * P + p) * DH + d;
                    *(unsigned*)((__half*)g_qkv_h + di) = ph2(v0, v1);
                }
            } else {
#pragma unroll
                for (int nt = 0; nt < 4; nt++) {
                    const int n = bn + n0 + nt * 8 + 2 * t;
                    float2 st;
                    st.x = cc[mt][nt][half_ * 2 + 0] + __ldg(bias + n);
                    st.y = cc[mt][nt][half_ * 2 + 1] + __ldg(bias + n + 1);
                    *(float2*)(out + (size_t)m * DIM + n) = st;
                }
            }
        }
    }
}

// ---------------- attention ----------------
__global__ void __launch_bounds__(288, 2) attn_h(int dummy) {
    __shared__ __align__(16) __half qs[144 * 40];
    __shared__ __align__(16) __half ks[144 * 40];
    __shared__ __align__(16) __half vT[32 * 152];

    const int bh = blockIdx.x;
    const int bn = bh / HEADS, h = bh % HEADS;
    const int wt = bn / MW;
    const int tid = threadIdx.x;
    const int w = tid >> 5, lane = tid & 31;
    const int g = lane >> 2, t = lane & 3;

    const size_t hp = (size_t)P * DH;
    const size_t plane = (size_t)BN * HEADS * hp;
    const size_t qbase = ((size_t)bn * HEADS + h) * hp;
    const __half* gq = (const __half*)g_qkv_h + qbase;
    const __half* gk = (const __half*)g_qkv_h + plane + qbase;
    const __half* gv = (const __half*)g_qkv_h + 2 * plane + qbase;

    for (int f = tid; f < 576; f += 288) {
        const int p = f >> 2, c = (f & 3) * 8;
        *(uint4*)(qs + p * 40 + c) = *(const uint4*)(gq + p * 32 + c);
        *(uint4*)(ks + p * 40 + c) = *(const uint4*)(gk + p * 32 + c);
    }
    for (int f = tid; f < 2304; f += 288) {
        const int p = f >> 4, d = (f & 15) * 2;
        __half2 v2 = *(const __half2*)(gv + p * 32 + d);
        vT[d * 152 + p] = __low2half(v2);
        vT[(d + 1) * 152 + p] = __high2half(v2);
    }
    __syncthreads();

    const int wr = w * 16;
    const unsigned sQ = (unsigned)__cvta_generic_to_shared(qs);
    const unsigned sK = (unsigned)__cvta_generic_to_shared(ks);
    const unsigned sV = (unsigned)__cvta_generic_to_shared(vT);

    const int qrow = wr + (lane & 15);
    const int qcol = (lane >> 4) * 8;
    const int krow = (lane >> 4) * 8 + (lane & 7);
    const int kcol = ((lane >> 3) & 1) * 8;

    // ---- S = Q @ K^T ----
    float s[18][4] = {};
#pragma unroll
    for (int kk = 0; kk < DH; kk += 16) {
        unsigned af[4];
        ldsm4(af, sQ + (qrow * 40 + kk + qcol) * 2);
#pragma unroll
        for (int nt2 = 0; nt2 < 9; nt2++) {
            unsigned r[4];
            ldsm4(r, sK + ((krow + nt2 * 16) * 40 + kk + kcol) * 2);
            unsigned b0[2] = { r[0], r[1] };
            unsigned b1[2] = { r[2], r[3] };
            mma_f16(s[2 * nt2], af, b0);
            mma_f16(s[2 * nt2 + 1], af, b1);
        }
    }

    // ---- + bias + mask (fp16, pre-scaled by log2e) ----
    {
        const __half* gb = (const __half*)g_bias_h + ((size_t)(wt * HEADS + h)) * PSQ;
        const __half* mk = (const __half*)g_mask_h + (size_t)bn * PSQ;
        const int r0 = wr + g, r1 = r0 + 8;
#pragma unroll
        for (int nt = 0; nt < 18; nt++) {
            const int c = nt * 8 + 2 * t;
            __half2 a0 = __hadd2(*(const __half2*)(gb + (size_t)r0 * P + c),
                                 *(const __half2*)(mk + (size_t)r0 * P + c));
            __half2 a1 = __hadd2(*(const __half2*)(gb + (size_t)r1 * P + c),
                                 *(const __half2*)(mk + (size_t)r1 * P + c));
            float2 f0 = __half22float2(a0);
            float2 f1 = __half22float2(a1);
            s[nt][0] += f0.x; s[nt][1] += f0.y;
            s[nt][2] += f1.x; s[nt][3] += f1.y;
        }
    }

    // ---- softmax: f16x2 ex2 producing AV A-fragments directly ----
    unsigned pa[18], pb[18];   // probs: pa = rows r0 pair, pb = rows r1 pair
    float i0, i1;
    {
        float mx0 = -1e30f, mx1 = -1e30f;
#pragma unroll
        for (int nt = 0; nt < 18; nt++) {
            mx0 = fmaxf(mx0, fmaxf(s[nt][0], s[nt][1]));
            mx1 = fmaxf(mx1, fmaxf(s[nt][2], s[nt][3]));
        }
        mx0 = fmaxf(mx0, __shfl_xor_sync(0xffffffffu, mx0, 1));
        mx0 = fmaxf(mx0, __shfl_xor_sync(0xffffffffu, mx0, 2));
        mx1 = fmaxf(mx1, __shfl_xor_sync(0xffffffffu, mx1, 1));
        mx1 = fmaxf(mx1, __shfl_xor_sync(0xffffffffu, mx1, 2));
        float s0 = 0.f, s1 = 0.f;
#pragma unroll
        for (int nt = 0; nt < 18; nt++) {
            pa[nt] = ex2_h2(s[nt][0] - mx0, s[nt][1] - mx0);
            pb[nt] = ex2_h2(s[nt][2] - mx1, s[nt][3] - mx1);
            float2 fa = __half22float2(*(__half2*)&pa[nt]);
            float2 fb = __half22float2(*(__half2*)&pb[nt]);
            s0 += fa.x + fa.y;
            s1 += fb.x + fb.y;
        }
        s0 += __shfl_xor_sync(0xffffffffu, s0, 1);
        s0 += __shfl_xor_sync(0xffffffffu, s0, 2);
        s1 += __shfl_xor_sync(0xffffffffu, s1, 1);
        s1 += __shfl_xor_sync(0xffffffffu, s1, 2);
        i0 = 1.f / s0;
        i1 = 1.f / s1;
    }

    // ---- O = S @ V (unnormalized probs; scale after) ----
    {
        float o[4][4] = {};
        const int vrow = (lane >> 4) * 8 + (lane & 7);
        const int vcol = ((lane >> 3) & 1) * 8;
#pragma unroll
        for (int kb = 0; kb < 9; kb++) {
            unsigned a[4];
            a[0] = pa[2 * kb];
            a[1] = pb[2 * kb];
            a[2] = pa[2 * kb + 1];
            a[3] = pb[2 * kb + 1];
#pragma unroll
            for (int nt2 = 0; nt2 < 2; nt2++) {
                unsigned r[4];
                ldsm4(r, sV + ((vrow + nt2 * 16) * 152 + kb * 16 + vcol) * 2);
                unsigned b0[2] = { r[0], r[1] };
                unsigned b1[2] = { r[2], r[3] };
                mma_f16(o[nt2 * 2], a, b0);
                mma_f16(o[nt2 * 2 + 1], a, b1);
            }
        }
        __half* go = (__half*)g_xo_h + ((size_t)bn * P) * DIM + h * 32;
#pragma unroll
        for (int nt = 0; nt < 4; nt++) {
            const int col = nt * 8 + 2 * t;
            *(unsigned*)(go + (size_t)(wr + g) * DIM + col)     = ph2(o[nt][0] * i0, o[nt][1] * i0);
            *(unsigned*)(go + (size_t)(wr + g + 8) * DIM + col) = ph2(o[nt][2] * i1, o[nt][3] * i1);
        }
    }
}

// ---------------- launcher ----------------
extern "C" void kernel_launch(void* const* d_in, const int* in_sizes, int n_in,
                              void* d_out, int out_size) {
    const float* x          = (const float*)d_in[0];
    const float* mask       = (const float*)d_in[1];
    const float* w_qkv      = (const float*)d_in[2];
    const float* w_proj     = (const float*)d_in[3];
    const float* b_proj     = (const float*)d_in[4];
    const float* bias_table = (const float*)d_in[5];
    float* out = (float*)d_out;

    const int smem_gemm = (2 * 128 * 72 + 2 * 64 * 72) * 2;   // 55296 B
    cudaFuncSetAttribute(gemm_h<true>,
                         cudaFuncAttributeMaxDynamicSharedMemorySize, smem_gemm);
    cudaFuncSetAttribute(gemm_h<false>,
                         cudaFuncAttributeMaxDynamicSharedMemorySize, smem_gemm);

    prep_all<<<NB_TOT, 256>>>(x, mask, w_qkv, w_proj, bias_table);
    gemm_h<true><<<dim3(9, M_TOT / 128), 256, smem_gemm>>>(nullptr, nullptr);
    attn_h<<<BN * HEADS, 288>>>(0);
    gemm_h<false><<<dim3(3, M_TOT / 128), 256, smem_gemm>>>(b_proj, out);
}